// round 9
// baseline (speedup 1.0000x reference)
#include <cuda_runtime.h>
#include <math_constants.h>

// Problem constants
#define B_ 8
#define T_ 4096
#define D_ 512
#define NTOK (B_ * T_)      // 32768
#define TPB 256             // threads per block; each thread owns 2 d-indices
#define GRID 296            // 148 SMs * 2 blocks
#define TPI 4               // tokens per iteration
#define STRIDE (GRID * TPI) // 1184

typedef unsigned long long u64;

__device__ __forceinline__ u64 pack2(float lo, float hi) {
    u64 r; asm("mov.b64 %0, {%1, %2};" : "=l"(r) : "f"(lo), "f"(hi)); return r;
}
__device__ __forceinline__ void unpack2(u64 v, float& lo, float& hi) {
    asm("mov.b64 {%0, %1}, %2;" : "=f"(lo), "=f"(hi) : "l"(v));
}
__device__ __forceinline__ void fma2(u64& d, u64 a, u64 b) {
    asm("fma.rn.f32x2 %0, %1, %2, %0;" : "+l"(d) : "l"(a), "l"(b));
}
__device__ __forceinline__ u64 add2(u64 a, u64 b) {
    u64 r; asm("add.rn.f32x2 %0, %1, %2;" : "=l"(r) : "l"(a), "l"(b)); return r;
}
__device__ __forceinline__ u64 shfl_xor_u64(u64 v, int off) {
    float lo, hi; unpack2(v, lo, hi);
    lo = __shfl_xor_sync(0xffffffffu, lo, off);
    hi = __shfl_xor_sync(0xffffffffu, hi, off);
    return pack2(lo, hi);
}

__global__ void __launch_bounds__(TPB, 2)
router_kernel(const float* __restrict__ m0, const float* __restrict__ m1,
              const float* __restrict__ m2, const float* __restrict__ m3,
              const float* __restrict__ Wtop, const float* __restrict__ btop,
              const float* __restrict__ Wsoft, const float* __restrict__ bsoft,
              const float* __restrict__ alpha, float* __restrict__ out)
{
    // Packed partials: [token][logit-pair p][thread]
    //   p=0: top logits (0,1)   p=1: top logits (2,3)
    //   p=2: soft logits (0,1)  p=3: soft logits (2,3)
    __shared__ u64 s_part[TPI][4][TPB];               // 32 KB
    __shared__ __align__(16) u64 s_hard[TPI][2];      // aSig * hard_k   (pairs)
    __shared__ __align__(16) u64 s_soft[TPI][2];      // aInv * soft_k   (pairs)

    const int t = threadIdx.x;
    const int wid = t >> 5;
    const int lane = t & 31;

    // ---- One-time: weights for this thread's (d0,d1)=(2t,2t+1), packed f32x2 ----
    u64 w[8][4];
    {
        const float4* Wt4 = (const float4*)Wtop;
        const float4* Ws4 = (const float4*)Wsoft;
        #pragma unroll
        for (int j = 0; j < 4; j++) {
            float4 a0 = Wt4[j * 512 + 2 * t];
            float4 a1 = Wt4[j * 512 + 2 * t + 1];
            w[j][0] = pack2(a0.x, a1.x);
            w[j][1] = pack2(a0.y, a1.y);
            w[j][2] = pack2(a0.z, a1.z);
            w[j][3] = pack2(a0.w, a1.w);
            float4 b0 = Ws4[j * 512 + 2 * t];
            float4 b1 = Ws4[j * 512 + 2 * t + 1];
            w[4 + j][0] = pack2(b0.x, b1.x);
            w[4 + j][1] = pack2(b0.y, b1.y);
            w[4 + j][2] = pack2(b0.z, b1.z);
            w[4 + j][3] = pack2(b0.w, b1.w);
        }
    }
    const float aSig = 1.0f / (1.0f + __expf(-alpha[0]));
    const float aInv = 1.0f - aSig;

    const u64* q0 = (const u64*)m0;
    const u64* q1 = (const u64*)m1;
    const u64* q2 = (const u64*)m2;
    const u64* q3 = (const u64*)m3;
    u64* qo = (u64*)out;

    // ---- Prologue: load first iteration's tokens ----
    u64 dm[TPI][4];
    int tok0 = blockIdx.x * TPI;
    #pragma unroll
    for (int i = 0; i < TPI; i++) {
        int tk = tok0 + i;
        if (tk < NTOK) {
            int base = tk * (D_ / 2) + t;
            dm[i][0] = q0[base]; dm[i][1] = q1[base];
            dm[i][2] = q2[base]; dm[i][3] = q3[base];
        } else {
            dm[i][0] = dm[i][1] = dm[i][2] = dm[i][3] = 0ull;
        }
    }

    for (; tok0 < NTOK; tok0 += STRIDE) {
        // ---- GEMV partials (consume dm), packed STS.64 ----
        #pragma unroll
        for (int i = 0; i < TPI; i++) {
            u64 acc[8];
            #pragma unroll
            for (int j = 0; j < 8; j++) acc[j] = 0ull;
            #pragma unroll
            for (int k = 0; k < 4; k++) {
                #pragma unroll
                for (int j = 0; j < 8; j++) fma2(acc[j], dm[i][k], w[j][k]);
            }
            #pragma unroll
            for (int p = 0; p < 4; p++) {
                float a0, a1, b0, b1;
                unpack2(acc[2 * p],     a0, a1);
                unpack2(acc[2 * p + 1], b0, b1);
                s_part[i][p][t] = pack2(a0 + a1, b0 + b1);
            }
        }

        // ---- Prefetch NEXT iteration into dm (flies during reduce+epilogue) ----
        {
            int nt0 = tok0 + STRIDE;
            #pragma unroll
            for (int i = 0; i < TPI; i++) {
                int tk = nt0 + i;
                if (tk < NTOK) {
                    int base = tk * (D_ / 2) + t;
                    dm[i][0] = q0[base]; dm[i][1] = q1[base];
                    dm[i][2] = q2[base]; dm[i][3] = q3[base];
                }
            }
        }
        __syncthreads();

        // ---- Reduce + routing: warp w -> (token i = w>>1, half h = w&1) ----
        {
            const int i = wid >> 1;
            const int h = wid & 1;          // 0: top/hard, 1: soft
            u64 r0, r1;                      // logit pairs (0,1) and (2,3) of this half
            {
                const ulonglong2* rowa = (const ulonglong2*)&s_part[i][2 * h][0];
                const ulonglong2* rowb = (const ulonglong2*)&s_part[i][2 * h + 1][0];
                ulonglong2 a0 = rowa[lane],      a1 = rowa[lane + 32];
                ulonglong2 a2 = rowa[lane + 64], a3 = rowa[lane + 96];
                ulonglong2 b0 = rowb[lane],      b1 = rowb[lane + 32];
                ulonglong2 b2 = rowb[lane + 64], b3 = rowb[lane + 96];
                r0 = add2(add2(add2(a0.x, a0.y), add2(a1.x, a1.y)),
                          add2(add2(a2.x, a2.y), add2(a3.x, a3.y)));
                r1 = add2(add2(add2(b0.x, b0.y), add2(b1.x, b1.y)),
                          add2(add2(b2.x, b2.y), add2(b3.x, b3.y)));
            }
            #pragma unroll
            for (int off = 16; off > 0; off >>= 1) {
                r0 = add2(r0, shfl_xor_u64(r0, off));
                r1 = add2(r1, shfl_xor_u64(r1, off));
            }

            float L0, L1, L2, L3;
            unpack2(r0, L0, L1);
            unpack2(r1, L2, L3);

            if (h == 0) {
                // hard path: top-2 softmax scatter, scaled by aSig
                L0 += btop[0]; L1 += btop[1]; L2 += btop[2]; L3 += btop[3];
                float Tv[4] = {L0, L1, L2, L3};
                int i1 = 0; float v1 = Tv[0];
                #pragma unroll
                for (int k = 1; k < 4; k++) if (Tv[k] > v1) { v1 = Tv[k]; i1 = k; }
                int i2 = -1; float v2 = -CUDART_INF_F;
                #pragma unroll
                for (int k = 0; k < 4; k++) if (k != i1 && Tv[k] > v2) { v2 = Tv[k]; i2 = k; }
                float pp1 = aSig / (1.0f + __expf(v2 - v1));
                float pp2 = aSig - pp1;
                float hk[4];
                #pragma unroll
                for (int k = 0; k < 4; k++)
                    hk[k] = (k == i1) ? pp1 : ((k == i2) ? pp2 : 0.0f);
                if (lane == 0) {
                    s_hard[i][0] = pack2(hk[0], hk[1]);
                    s_hard[i][1] = pack2(hk[2], hk[3]);
                }
            } else {
                // soft path: softmax scaled by aInv
                L0 += bsoft[0]; L1 += bsoft[1]; L2 += bsoft[2]; L3 += bsoft[3];
                float ms = fmaxf(fmaxf(L0, L1), fmaxf(L2, L3));
                float e0 = __expf(L0 - ms), e1 = __expf(L1 - ms);
                float e2 = __expf(L2 - ms), e3 = __expf(L3 - ms);
                float sc = aInv / (e0 + e1 + e2 + e3);
                if (lane == 0) {
                    s_soft[i][0] = pack2(e0 * sc, e1 * sc);
                    s_soft[i][1] = pack2(e2 * sc, e3 * sc);
                }
            }
        }
        __syncthreads();

        // ---- Epilogue: reload m (L1/L2 hit), blend halves, weighted sum, store ----
        #pragma unroll
        for (int i = 0; i < TPI; i++) {
            int tk = tok0 + i;
            if (tk < NTOK) {
                int base = tk * (D_ / 2) + t;
                u64 c0 = q0[base], c1 = q1[base], c2 = q2[base], c3 = q3[base];
                u64 w01 = add2(s_hard[i][0], s_soft[i][0]);
                u64 w23 = add2(s_hard[i][1], s_soft[i][1]);
                float w0, w1, w2, w3;
                unpack2(w01, w0, w1);
                unpack2(w23, w2, w3);
                u64 o = 0ull;
                fma2(o, c0, pack2(w0, w0));
                fma2(o, c1, pack2(w1, w1));
                fma2(o, c2, pack2(w2, w2));
                fma2(o, c3, pack2(w3, w3));
                qo[base] = o;
            }
        }
    }
}

extern "C" void kernel_launch(void* const* d_in, const int* in_sizes, int n_in,
                              void* d_out, int out_size) {
    (void)in_sizes; (void)n_in; (void)out_size;
    router_kernel<<<GRID, TPB>>>(
        (const float*)d_in[0], (const float*)d_in[1],
        (const float*)d_in[2], (const float*)d_in[3],
        (const float*)d_in[4], (const float*)d_in[5],
        (const float*)d_in[6], (const float*)d_in[7],
        (const float*)d_in[8], (float*)d_out);
}

// round 10
// speedup vs baseline: 1.0749x; 1.0749x over previous
#include <cuda_runtime.h>
#include <math_constants.h>

// Problem constants
#define B_ 8
#define T_ 4096
#define D_ 512
#define NTOK (B_ * T_)      // 32768
#define TPB 256             // threads per block; thread t owns d = {2t, 2t+1}
#define GRID 296            // 148 SMs * 2 blocks
#define TPI 4               // tokens per iteration
#define STRIDE (GRID * TPI) // 1184

// Dynamic smem layout (bytes):
//   mt  [2 stages][4 tok][2 kpair][256 thr][2 u64]   : 65536
//   s_part [4 tok][4 pair][256 thr] u64              : 32768  (off 65536)
//   s_hard [4][2] u64, s_soft [4][2] u64             : 128    (off 98304)
#define MT_OFF    0
#define SP_OFF    65536
#define HW_OFF    98304
#define SW_OFF    98368
#define SMEM_BYTES 98432

typedef unsigned long long u64;

__device__ __forceinline__ u64 pack2(float lo, float hi) {
    u64 r; asm("mov.b64 %0, {%1, %2};" : "=l"(r) : "f"(lo), "f"(hi)); return r;
}
__device__ __forceinline__ void unpack2(u64 v, float& lo, float& hi) {
    asm("mov.b64 {%0, %1}, %2;" : "=f"(lo), "=f"(hi) : "l"(v));
}
__device__ __forceinline__ void fma2(u64& d, u64 a, u64 b) {
    asm("fma.rn.f32x2 %0, %1, %2, %0;" : "+l"(d) : "l"(a), "l"(b));
}
__device__ __forceinline__ u64 add2(u64 a, u64 b) {
    u64 r; asm("add.rn.f32x2 %0, %1, %2;" : "=l"(r) : "l"(a), "l"(b)); return r;
}
__device__ __forceinline__ u64 shfl_xor_u64(u64 v, int off) {
    float lo, hi; unpack2(v, lo, hi);
    lo = __shfl_xor_sync(0xffffffffu, lo, off);
    hi = __shfl_xor_sync(0xffffffffu, hi, off);
    return pack2(lo, hi);
}
__device__ __forceinline__ void cp8(unsigned dst, const void* src) {
    asm volatile("cp.async.ca.shared.global [%0], [%1], 8;"
                 :: "r"(dst), "l"(src) : "memory");
}
__device__ __forceinline__ void cp_commit() {
    asm volatile("cp.async.commit_group;" ::: "memory");
}
__device__ __forceinline__ void cp_wait1() {
    asm volatile("cp.async.wait_group 1;" ::: "memory");
}

__global__ void __launch_bounds__(TPB, 2)
router_kernel(const float* __restrict__ m0, const float* __restrict__ m1,
              const float* __restrict__ m2, const float* __restrict__ m3,
              const float* __restrict__ Wtop, const float* __restrict__ btop,
              const float* __restrict__ Wsoft, const float* __restrict__ bsoft,
              const float* __restrict__ alpha, float* __restrict__ out)
{
    extern __shared__ __align__(16) char sm[];
    unsigned sm_u32;
    asm("{ .reg .u64 tmp; cvta.to.shared.u64 tmp, %1; cvt.u32.u64 %0, tmp; }"
        : "=r"(sm_u32) : "l"(sm));

    const int t = threadIdx.x;
    const int wid = t >> 5;
    const int lane = t & 31;

    // ---- One-time: weights for (d0,d1)=(2t,2t+1), packed f32x2 ----
    u64 w[8][4];
    {
        const float4* Wt4 = (const float4*)Wtop;
        const float4* Ws4 = (const float4*)Wsoft;
        #pragma unroll
        for (int j = 0; j < 4; j++) {
            float4 a0 = Wt4[j * 512 + 2 * t];
            float4 a1 = Wt4[j * 512 + 2 * t + 1];
            w[j][0] = pack2(a0.x, a1.x);
            w[j][1] = pack2(a0.y, a1.y);
            w[j][2] = pack2(a0.z, a1.z);
            w[j][3] = pack2(a0.w, a1.w);
            float4 b0 = Ws4[j * 512 + 2 * t];
            float4 b1 = Ws4[j * 512 + 2 * t + 1];
            w[4 + j][0] = pack2(b0.x, b1.x);
            w[4 + j][1] = pack2(b0.y, b1.y);
            w[4 + j][2] = pack2(b0.z, b1.z);
            w[4 + j][3] = pack2(b0.w, b1.w);
        }
    }
    const float aSig = 1.0f / (1.0f + __expf(-alpha[0]));
    const float aInv = 1.0f - aSig;

    const u64* q0 = (const u64*)m0;
    const u64* q1 = (const u64*)m1;
    const u64* q2 = (const u64*)m2;
    const u64* q3 = (const u64*)m3;
    u64* qo = (u64*)out;

    // mt slot addr for (stage, i, k): thread-private slot at t*16 + (k&1)*8
    // stage stride 32768, token stride 8192, kpair stride 4096.
    const unsigned mt_t = sm_u32 + MT_OFF + t * 16;

    // ---- Prologue: issue stages 0 and 1 ----
    const int tok_b = blockIdx.x * TPI;
    #pragma unroll
    for (int s = 0; s < 2; s++) {
        int tk0 = tok_b + s * STRIDE;
        if (tk0 < NTOK) {
            #pragma unroll
            for (int i = 0; i < TPI; i++) {
                int base = (tk0 + i) * (D_ / 2) + t;
                unsigned d = mt_t + s * 32768 + i * 8192;
                cp8(d,        q0 + base);
                cp8(d + 8,    q1 + base);
                cp8(d + 4096, q2 + base);
                cp8(d + 4104, q3 + base);
            }
        }
        cp_commit();
    }

    int stage = 0;
    for (int tok0 = tok_b; tok0 < NTOK; tok0 += STRIDE, stage ^= 1) {
        // ---- Wait for this thread's current tile (thread-private: no barrier) ----
        cp_wait1();

        // ---- Load tile to regs (LDS.128), GEMV partials, STS ----
        u64 dm[TPI][4];
        #pragma unroll
        for (int i = 0; i < TPI; i++) {
            const ulonglong2* p01 = (const ulonglong2*)(sm + (size_t)(MT_OFF) + stage * 32768 + i * 8192 + t * 16);
            const ulonglong2* p23 = (const ulonglong2*)(sm + (size_t)(MT_OFF) + stage * 32768 + i * 8192 + 4096 + t * 16);
            ulonglong2 v01 = *p01;   // (m0, m1) at this thread's d-pair
            ulonglong2 v23 = *p23;   // (m2, m3)
            dm[i][0] = v01.x; dm[i][1] = v01.y;
            dm[i][2] = v23.x; dm[i][3] = v23.y;

            u64 acc[8];
            #pragma unroll
            for (int j = 0; j < 8; j++) acc[j] = 0ull;
            #pragma unroll
            for (int k = 0; k < 4; k++) {
                #pragma unroll
                for (int j = 0; j < 8; j++) fma2(acc[j], dm[i][k], w[j][k]);
            }
            #pragma unroll
            for (int p = 0; p < 4; p++) {
                float a0, a1, b0, b1;
                unpack2(acc[2 * p],     a0, a1);
                unpack2(acc[2 * p + 1], b0, b1);
                *(u64*)(sm + (size_t)SP_OFF + i * 8192 + p * 2048 + t * 8) =
                    pack2(a0 + a1, b0 + b1);
            }
        }

        // ---- Issue prefetch for iter n+2 into the stage just consumed ----
        {
            int tk0 = tok0 + 2 * STRIDE;
            if (tk0 < NTOK) {
                #pragma unroll
                for (int i = 0; i < TPI; i++) {
                    int base = (tk0 + i) * (D_ / 2) + t;
                    unsigned d = mt_t + stage * 32768 + i * 8192;
                    cp8(d,        q0 + base);
                    cp8(d + 8,    q1 + base);
                    cp8(d + 4096, q2 + base);
                    cp8(d + 4104, q3 + base);
                }
            }
            cp_commit();
        }
        __syncthreads();

        // ---- Reduce + routing: warp w -> (token i = w>>1, half h = w&1) ----
        {
            const int i = wid >> 1;
            const int h = wid & 1;          // 0: top/hard, 1: soft
            const ulonglong2* rowa = (const ulonglong2*)(sm + (size_t)SP_OFF + i * 8192 + (2 * h) * 2048);
            const ulonglong2* rowb = (const ulonglong2*)(sm + (size_t)SP_OFF + i * 8192 + (2 * h + 1) * 2048);
            ulonglong2 a0 = rowa[lane],      a1 = rowa[lane + 32];
            ulonglong2 a2 = rowa[lane + 64], a3 = rowa[lane + 96];
            ulonglong2 b0 = rowb[lane],      b1 = rowb[lane + 32];
            ulonglong2 b2 = rowb[lane + 64], b3 = rowb[lane + 96];
            u64 r0 = add2(add2(add2(a0.x, a0.y), add2(a1.x, a1.y)),
                          add2(add2(a2.x, a2.y), add2(a3.x, a3.y)));
            u64 r1 = add2(add2(add2(b0.x, b0.y), add2(b1.x, b1.y)),
                          add2(add2(b2.x, b2.y), add2(b3.x, b3.y)));
            #pragma unroll
            for (int off = 16; off > 0; off >>= 1) {
                r0 = add2(r0, shfl_xor_u64(r0, off));
                r1 = add2(r1, shfl_xor_u64(r1, off));
            }

            float L0, L1, L2, L3;
            unpack2(r0, L0, L1);
            unpack2(r1, L2, L3);

            if (h == 0) {
                // hard: top-2 softmax scatter scaled by aSig (lax.top_k tie rule)
                L0 += btop[0]; L1 += btop[1]; L2 += btop[2]; L3 += btop[3];
                float Tv[4] = {L0, L1, L2, L3};
                int i1 = 0; float v1 = Tv[0];
                #pragma unroll
                for (int k = 1; k < 4; k++) if (Tv[k] > v1) { v1 = Tv[k]; i1 = k; }
                int i2 = -1; float v2 = -CUDART_INF_F;
                #pragma unroll
                for (int k = 0; k < 4; k++) if (k != i1 && Tv[k] > v2) { v2 = Tv[k]; i2 = k; }
                float pp1 = aSig / (1.0f + __expf(v2 - v1));
                float pp2 = aSig - pp1;
                float hk[4];
                #pragma unroll
                for (int k = 0; k < 4; k++)
                    hk[k] = (k == i1) ? pp1 : ((k == i2) ? pp2 : 0.0f);
                if (lane == 0) {
                    *(u64*)(sm + (size_t)HW_OFF + i * 16)     = pack2(hk[0], hk[1]);
                    *(u64*)(sm + (size_t)HW_OFF + i * 16 + 8) = pack2(hk[2], hk[3]);
                }
            } else {
                // soft: softmax scaled by aInv
                L0 += bsoft[0]; L1 += bsoft[1]; L2 += bsoft[2]; L3 += bsoft[3];
                float ms = fmaxf(fmaxf(L0, L1), fmaxf(L2, L3));
                float e0 = __expf(L0 - ms), e1 = __expf(L1 - ms);
                float e2 = __expf(L2 - ms), e3 = __expf(L3 - ms);
                float sc = aInv / (e0 + e1 + e2 + e3);
                if (lane == 0) {
                    *(u64*)(sm + (size_t)SW_OFF + i * 16)     = pack2(e0 * sc, e1 * sc);
                    *(u64*)(sm + (size_t)SW_OFF + i * 16 + 8) = pack2(e2 * sc, e3 * sc);
                }
            }
        }
        __syncthreads();

        // ---- Epilogue: blend halves, weighted sum from dm regs, store ----
        #pragma unroll
        for (int i = 0; i < TPI; i++) {
            u64 h01 = *(const u64*)(sm + (size_t)HW_OFF + i * 16);
            u64 h23 = *(const u64*)(sm + (size_t)HW_OFF + i * 16 + 8);
            u64 s01 = *(const u64*)(sm + (size_t)SW_OFF + i * 16);
            u64 s23 = *(const u64*)(sm + (size_t)SW_OFF + i * 16 + 8);
            float w0, w1, w2, w3;
            unpack2(add2(h01, s01), w0, w1);
            unpack2(add2(h23, s23), w2, w3);
            u64 o = 0ull;
            fma2(o, dm[i][0], pack2(w0, w0));
            fma2(o, dm[i][1], pack2(w1, w1));
            fma2(o, dm[i][2], pack2(w2, w2));
            fma2(o, dm[i][3], pack2(w3, w3));
            qo[(tok0 + i) * (D_ / 2) + t] = o;
        }
    }
}

extern "C" void kernel_launch(void* const* d_in, const int* in_sizes, int n_in,
                              void* d_out, int out_size) {
    (void)in_sizes; (void)n_in; (void)out_size;
    cudaFuncSetAttribute(router_kernel,
                         cudaFuncAttributeMaxDynamicSharedMemorySize, SMEM_BYTES);
    router_kernel<<<GRID, TPB, SMEM_BYTES>>>(
        (const float*)d_in[0], (const float*)d_in[1],
        (const float*)d_in[2], (const float*)d_in[3],
        (const float*)d_in[4], (const float*)d_in[5],
        (const float*)d_in[6], (const float*)d_in[7],
        (const float*)d_in[8], (float*)d_out);
}

// round 11
// speedup vs baseline: 1.0800x; 1.0047x over previous
#include <cuda_runtime.h>
#include <math_constants.h>

// Problem constants
#define NTOK 32768
#define TPB 256             // thread t owns d-pair (2t, 2t+1)
#define GRID 296            // 148 SMs * 2 CTAs
#define TPI 3               // tokens per iteration
#define STRIDE (GRID * TPI) // 888

// Dynamic smem layout (bytes):
//   stages [3][TPI tok][4 mat][256 thr] u64 : 73728
//   s_part [TPI tok][4 pair][256 thr] u64   : 24576 (off 73728)
//   wk     [2 parity][2 kind][TPI][2] u64   : 192   (off 98304)
#define ST_OFF 0
#define STG_SZ 24576
#define SP_OFF 73728
#define WK_OFF 98304
#define SMEM_BYTES 98496

typedef unsigned long long u64;

__device__ __forceinline__ u64 pack2(float lo, float hi) {
    u64 r; asm("mov.b64 %0, {%1, %2};" : "=l"(r) : "f"(lo), "f"(hi)); return r;
}
__device__ __forceinline__ void unpack2(u64 v, float& lo, float& hi) {
    asm("mov.b64 {%0, %1}, %2;" : "=f"(lo), "=f"(hi) : "l"(v));
}
__device__ __forceinline__ void fma2(u64& d, u64 a, u64 b) {
    asm("fma.rn.f32x2 %0, %1, %2, %0;" : "+l"(d) : "l"(a), "l"(b));
}
__device__ __forceinline__ u64 add2(u64 a, u64 b) {
    u64 r; asm("add.rn.f32x2 %0, %1, %2;" : "=l"(r) : "l"(a), "l"(b)); return r;
}
__device__ __forceinline__ u64 shfl_xor_u64(u64 v, int off) {
    float lo, hi; unpack2(v, lo, hi);
    lo = __shfl_xor_sync(0xffffffffu, lo, off);
    hi = __shfl_xor_sync(0xffffffffu, hi, off);
    return pack2(lo, hi);
}
__device__ __forceinline__ void cp8(unsigned dst, const void* src) {
    asm volatile("cp.async.ca.shared.global [%0], [%1], 8;"
                 :: "r"(dst), "l"(src) : "memory");
}
__device__ __forceinline__ void cp_commit() {
    asm volatile("cp.async.commit_group;" ::: "memory");
}
__device__ __forceinline__ void cp_wait1() {
    asm volatile("cp.async.wait_group 1;" ::: "memory");
}

__global__ void __launch_bounds__(TPB, 2)
router_kernel(const float* __restrict__ m0, const float* __restrict__ m1,
              const float* __restrict__ m2, const float* __restrict__ m3,
              const float* __restrict__ Wtop, const float* __restrict__ btop,
              const float* __restrict__ Wsoft, const float* __restrict__ bsoft,
              const float* __restrict__ alpha, float* __restrict__ out)
{
    extern __shared__ __align__(16) char sm[];
    unsigned sm_u32;
    asm("{ .reg .u64 tmp; cvta.to.shared.u64 tmp, %1; cvt.u32.u64 %0, tmp; }"
        : "=r"(sm_u32) : "l"(sm));

    const int t = threadIdx.x;
    const int wid = t >> 5;
    const int lane = t & 31;

    // ---- One-time: weights for (d0,d1)=(2t,2t+1), packed f32x2 ----
    u64 w[8][4];
    {
        const float4* Wt4 = (const float4*)Wtop;
        const float4* Ws4 = (const float4*)Wsoft;
        #pragma unroll
        for (int j = 0; j < 4; j++) {
            float4 a0 = Wt4[j * 512 + 2 * t];
            float4 a1 = Wt4[j * 512 + 2 * t + 1];
            w[j][0] = pack2(a0.x, a1.x);
            w[j][1] = pack2(a0.y, a1.y);
            w[j][2] = pack2(a0.z, a1.z);
            w[j][3] = pack2(a0.w, a1.w);
            float4 b0 = Ws4[j * 512 + 2 * t];
            float4 b1 = Ws4[j * 512 + 2 * t + 1];
            w[4 + j][0] = pack2(b0.x, b1.x);
            w[4 + j][1] = pack2(b0.y, b1.y);
            w[4 + j][2] = pack2(b0.z, b1.z);
            w[4 + j][3] = pack2(b0.w, b1.w);
        }
    }
    const float aSig = 1.0f / (1.0f + __expf(-alpha[0]));
    const float aInv = 1.0f - aSig;

    const u64* q0 = (const u64*)m0;
    const u64* q1 = (const u64*)m1;
    const u64* q2 = (const u64*)m2;
    const u64* q3 = (const u64*)m3;
    u64* qo = (u64*)out;

    const int tok_b = blockIdx.x * TPI;
    const unsigned st_t = sm_u32 + ST_OFF + t * 8;   // this thread's slot base

    // ---- Prologue: issue stages 0 and 1 (thread-private slots) ----
    #pragma unroll
    for (int s = 0; s < 2; s++) {
        int tk0 = tok_b + s * STRIDE;
        #pragma unroll
        for (int i = 0; i < TPI; i++) {
            int tk = tk0 + i;
            if (tk < NTOK) {
                int base = tk * 256 + t;
                unsigned d = st_t + s * STG_SZ + i * 8192;
                cp8(d,        q0 + base);
                cp8(d + 2048, q1 + base);
                cp8(d + 4096, q2 + base);
                cp8(d + 6144, q3 + base);
            }
        }
        cp_commit();
    }

    int sn = 0;      // current stage = n % 3
    int q = 0;       // parity = n & 1
    int tok0 = tok_b;
    for (; tok0 < NTOK; tok0 += STRIDE) {
        // ---- Wait this thread's current tile (thread-private; no barrier) ----
        cp_wait1();

        // ---- GEMV partials for TPI tokens (read stage sn via LDS) ----
        #pragma unroll
        for (int i = 0; i < TPI; i++) {
            const char* sb = sm + (size_t)(ST_OFF + sn * STG_SZ + i * 8192) + t * 8;
            u64 mv0 = *(const u64*)(sb);
            u64 mv1 = *(const u64*)(sb + 2048);
            u64 mv2 = *(const u64*)(sb + 4096);
            u64 mv3 = *(const u64*)(sb + 6144);

            u64 acc[8];
            #pragma unroll
            for (int j = 0; j < 8; j++) acc[j] = 0ull;
            #pragma unroll
            for (int j = 0; j < 8; j++) fma2(acc[j], mv0, w[j][0]);
            #pragma unroll
            for (int j = 0; j < 8; j++) fma2(acc[j], mv1, w[j][1]);
            #pragma unroll
            for (int j = 0; j < 8; j++) fma2(acc[j], mv2, w[j][2]);
            #pragma unroll
            for (int j = 0; j < 8; j++) fma2(acc[j], mv3, w[j][3]);
            #pragma unroll
            for (int p = 0; p < 4; p++) {
                float a0, a1, b0, b1;
                unpack2(acc[2 * p],     a0, a1);
                unpack2(acc[2 * p + 1], b0, b1);
                *(u64*)(sm + (size_t)SP_OFF + i * 8192 + p * 2048 + t * 8) =
                    pack2(a0 + a1, b0 + b1);
            }
        }

        // ---- SINGLE barrier: publishes partials(n) and wk(n-1) ----
        __syncthreads();

        // ---- Reduce + routing(n): warps 0..5 -> (token i = w>>1, half h = w&1)
        if (wid < 2 * TPI) {
            const int i = wid >> 1;
            const int h = wid & 1;          // 0: top/hard, 1: soft
            const ulonglong2* rowa = (const ulonglong2*)(sm + (size_t)SP_OFF + i * 8192 + (2 * h) * 2048);
            const ulonglong2* rowb = (const ulonglong2*)(sm + (size_t)SP_OFF + i * 8192 + (2 * h + 1) * 2048);
            ulonglong2 a0 = rowa[lane],      a1 = rowa[lane + 32];
            ulonglong2 a2 = rowa[lane + 64], a3 = rowa[lane + 96];
            ulonglong2 b0 = rowb[lane],      b1 = rowb[lane + 32];
            ulonglong2 b2 = rowb[lane + 64], b3 = rowb[lane + 96];
            u64 r0 = add2(add2(add2(a0.x, a0.y), add2(a1.x, a1.y)),
                          add2(add2(a2.x, a2.y), add2(a3.x, a3.y)));
            u64 r1 = add2(add2(add2(b0.x, b0.y), add2(b1.x, b1.y)),
                          add2(add2(b2.x, b2.y), add2(b3.x, b3.y)));
            #pragma unroll
            for (int off = 16; off > 0; off >>= 1) {
                r0 = add2(r0, shfl_xor_u64(r0, off));
                r1 = add2(r1, shfl_xor_u64(r1, off));
            }
            float L0, L1, L2, L3;
            unpack2(r0, L0, L1);
            unpack2(r1, L2, L3);

            char* wkp = sm + (size_t)WK_OFF + ((q * 2 + h) * TPI + i) * 16;
            if (h == 0) {
                L0 += btop[0]; L1 += btop[1]; L2 += btop[2]; L3 += btop[3];
                float Tv[4] = {L0, L1, L2, L3};
                int i1 = 0; float v1 = Tv[0];
                #pragma unroll
                for (int k = 1; k < 4; k++) if (Tv[k] > v1) { v1 = Tv[k]; i1 = k; }
                int i2 = -1; float v2 = -CUDART_INF_F;
                #pragma unroll
                for (int k = 0; k < 4; k++) if (k != i1 && Tv[k] > v2) { v2 = Tv[k]; i2 = k; }
                float pp1 = aSig / (1.0f + __expf(v2 - v1));
                float pp2 = aSig - pp1;
                float hk[4];
                #pragma unroll
                for (int k = 0; k < 4; k++)
                    hk[k] = (k == i1) ? pp1 : ((k == i2) ? pp2 : 0.0f);
                if (lane == 0) {
                    *(u64*)(wkp)     = pack2(hk[0], hk[1]);
                    *(u64*)(wkp + 8) = pack2(hk[2], hk[3]);
                }
            } else {
                L0 += bsoft[0]; L1 += bsoft[1]; L2 += bsoft[2]; L3 += bsoft[3];
                float ms = fmaxf(fmaxf(L0, L1), fmaxf(L2, L3));
                float e0 = __expf(L0 - ms), e1 = __expf(L1 - ms);
                float e2 = __expf(L2 - ms), e3 = __expf(L3 - ms);
                float sc = aInv / (e0 + e1 + e2 + e3);
                if (lane == 0) {
                    *(u64*)(wkp)     = pack2(e0 * sc, e1 * sc);
                    *(u64*)(wkp + 8) = pack2(e2 * sc, e3 * sc);
                }
            }
        }

        // ---- Epilogue(n-1): wk[1-q], m from stage (sn+2)%3 (thread-own slots)
        if (tok0 != tok_b) {
            const int tokp = tok0 - STRIDE;
            const int sp = (sn + 2) % 3;
            #pragma unroll
            for (int i = 0; i < TPI; i++) {
                int tk = tokp + i;
                if (tk < NTOK) {
                    const char* sb = sm + (size_t)(ST_OFF + sp * STG_SZ + i * 8192) + t * 8;
                    u64 c0 = *(const u64*)(sb);
                    u64 c1 = *(const u64*)(sb + 2048);
                    u64 c2 = *(const u64*)(sb + 4096);
                    u64 c3 = *(const u64*)(sb + 6144);
                    const char* wh = sm + (size_t)WK_OFF + (((1 - q) * 2 + 0) * TPI + i) * 16;
                    const char* ws = sm + (size_t)WK_OFF + (((1 - q) * 2 + 1) * TPI + i) * 16;
                    float w0, w1, w2, w3;
                    unpack2(add2(*(const u64*)wh,       *(const u64*)ws),       w0, w1);
                    unpack2(add2(*(const u64*)(wh + 8), *(const u64*)(ws + 8)), w2, w3);
                    u64 o = 0ull;
                    fma2(o, c0, pack2(w0, w0));
                    fma2(o, c1, pack2(w1, w1));
                    fma2(o, c2, pack2(w2, w2));
                    fma2(o, c3, pack2(w3, w3));
                    qo[tk * 256 + t] = o;
                }
            }
        }

        // ---- Prefetch(n+2) into stage (sn+2)%3 (own slots; after own epilogue reads)
        {
            int tk0 = tok0 + 2 * STRIDE;
            #pragma unroll
            for (int i = 0; i < TPI; i++) {
                int tk = tk0 + i;
                if (tk < NTOK) {
                    int base = tk * 256 + t;
                    unsigned d = st_t + ((sn + 2) % 3) * STG_SZ + i * 8192;
                    cp8(d,        q0 + base);
                    cp8(d + 2048, q1 + base);
                    cp8(d + 4096, q2 + base);
                    cp8(d + 6144, q3 + base);
                }
            }
            cp_commit();
        }

        sn = (sn + 1) % 3;
        q ^= 1;
    }

    // ---- Final epilogue for the last iteration's tokens ----
    __syncthreads();
    {
        const int tokp = tok0 - STRIDE;           // last executed iteration
        const int sp = (sn + 2) % 3;              // its stage
        const int qp = 1 - q;                     // its parity
        #pragma unroll
        for (int i = 0; i < TPI; i++) {
            int tk = tokp + i;
            if (tk >= 0 && tk < NTOK) {
                const char* sb = sm + (size_t)(ST_OFF + sp * STG_SZ + i * 8192) + t * 8;
                u64 c0 = *(const u64*)(sb);
                u64 c1 = *(const u64*)(sb + 2048);
                u64 c2 = *(const u64*)(sb + 4096);
                u64 c3 = *(const u64*)(sb + 6144);
                const char* wh = sm + (size_t)WK_OFF + ((qp * 2 + 0) * TPI + i) * 16;
                const char* ws = sm + (size_t)WK_OFF + ((qp * 2 + 1) * TPI + i) * 16;
                float w0, w1, w2, w3;
                unpack2(add2(*(const u64*)wh,       *(const u64*)ws),       w0, w1);
                unpack2(add2(*(const u64*)(wh + 8), *(const u64*)(ws + 8)), w2, w3);
                u64 o = 0ull;
                fma2(o, c0, pack2(w0, w0));
                fma2(o, c1, pack2(w1, w1));
                fma2(o, c2, pack2(w2, w2));
                fma2(o, c3, pack2(w3, w3));
                qo[tk * 256 + t] = o;
            }
        }
    }
}

extern "C" void kernel_launch(void* const* d_in, const int* in_sizes, int n_in,
                              void* d_out, int out_size) {
    (void)in_sizes; (void)n_in; (void)out_size;
    cudaFuncSetAttribute(router_kernel,
                         cudaFuncAttributeMaxDynamicSharedMemorySize, SMEM_BYTES);
    router_kernel<<<GRID, TPB, SMEM_BYTES>>>(
        (const float*)d_in[0], (const float*)d_in[1],
        (const float*)d_in[2], (const float*)d_in[3],
        (const float*)d_in[4], (const float*)d_in[5],
        (const float*)d_in[6], (const float*)d_in[7],
        (const float*)d_in[8], (float*)d_out);
}